// round 11
// baseline (speedup 1.0000x reference)
#include <cuda_runtime.h>

// RepeatDecoder: B=1024, S=200, H=128, VOCAB=100000
//   features = tanh(hidden + hidden[:,0:1,:])
//   scores   = features @ w_proj + b_proj ; mask PAD/INTEREST -> -inf
//   attn     = softmax(scores, axis=-1)
//   out[b, input_ids[b,s]] += attn[b,s]   (out zero elsewhere)
//
// R11: revert to R9 serial structure (memset -> fused compute+scatter, best
//      at 86.1us); compute kernel upgraded to 4-way position ILP per warp
//      (4 loads in flight, 4 interleaved shfl trees, 7 loop trips).

#define RD_VOCAB 100000
#define RD_PAD_ID (RD_VOCAB - 2)
#define RD_INTEREST_ID (RD_VOCAB - 1)
#define RD_B 1024
#define RD_S 200
#define RD_H 128
#define RD_THREADS 256
#define RD_WARPS (RD_THREADS / 32)

__device__ __forceinline__ float fast_tanhf(float x) {
    float r;
    asm("tanh.approx.f32 %0, %1;" : "=f"(r) : "f"(x));
    return r;
}

__device__ __forceinline__ float dot_tanh4(const float4 h, const float4 k4,
                                           const float4 w4) {
    float p = fast_tanhf(h.x + k4.x) * w4.x;
    p = fmaf(fast_tanhf(h.y + k4.y), w4.y, p);
    p = fmaf(fast_tanhf(h.z + k4.z), w4.z, p);
    p = fmaf(fast_tanhf(h.w + k4.w), w4.w, p);
    return p;
}

// ---------------------------------------------------------------------------
// Compute + scatter: scores -> softmax -> atomics (out pre-zeroed by memset).
// ---------------------------------------------------------------------------
__global__ __launch_bounds__(RD_THREADS)
void rd_compute_scatter_kernel(const float* __restrict__ hidden,
                               const int* __restrict__ ids,
                               const float* __restrict__ w_proj,
                               const float* __restrict__ b_proj,
                               float* __restrict__ out)
{
    __shared__ float s_scores[RD_S];
    __shared__ float s_part[RD_WARPS];
    __shared__ float s_bcast;

    const int b    = blockIdx.x;
    const int tid  = threadIdx.x;
    const int warp = tid >> 5;
    const int lane = tid & 31;

    const float* hb = hidden + (size_t)b * RD_S * RD_H;

    const float4 w4 = reinterpret_cast<const float4*>(w_proj)[lane];
    const float4 k4 = reinterpret_cast<const float4*>(hb)[lane];
    const float  bias = b_proj[0];

    // Four positions per warp per iteration: s = it*32 + warp + {0,8,16,24}.
    // 7 iterations cover 224 >= 200; per-position guards on the last trip.
    #pragma unroll 1
    for (int it = 0; it < 7; ++it) {
        const int s0 = it * 32 + warp;
        const int s1 = s0 + 8;
        const int s2 = s0 + 16;
        const int s3 = s0 + 24;
        const bool v1 = (s1 < RD_S);
        const bool v2 = (s2 < RD_S);
        const bool v3 = (s3 < RD_S);

        // issue all loads first (independent -> 4 in flight per warp)
        float4 h0, h1, h2, h3;
        if (s0 < RD_S) h0 = reinterpret_cast<const float4*>(hb + s0 * RD_H)[lane];
        if (v1)        h1 = reinterpret_cast<const float4*>(hb + s1 * RD_H)[lane];
        if (v2)        h2 = reinterpret_cast<const float4*>(hb + s2 * RD_H)[lane];
        if (v3)        h3 = reinterpret_cast<const float4*>(hb + s3 * RD_H)[lane];

        float p0 = 0.f, p1 = 0.f, p2 = 0.f, p3 = 0.f;
        if (s0 < RD_S) p0 = dot_tanh4(h0, k4, w4);
        if (v1)        p1 = dot_tanh4(h1, k4, w4);
        if (v2)        p2 = dot_tanh4(h2, k4, w4);
        if (v3)        p3 = dot_tanh4(h3, k4, w4);

        // four interleaved shuffle trees (independent chains -> ILP)
        #pragma unroll
        for (int off = 16; off > 0; off >>= 1) {
            p0 += __shfl_xor_sync(0xFFFFFFFFu, p0, off);
            p1 += __shfl_xor_sync(0xFFFFFFFFu, p1, off);
            p2 += __shfl_xor_sync(0xFFFFFFFFu, p2, off);
            p3 += __shfl_xor_sync(0xFFFFFFFFu, p3, off);
        }
        if (lane == 0) {
            if (s0 < RD_S) s_scores[s0] = p0 + bias;
            if (v1)        s_scores[s1] = p1 + bias;
            if (v2)        s_scores[s2] = p2 + bias;
            if (v3)        s_scores[s3] = p3 + bias;
        }
    }
    __syncthreads();

    // mask + softmax over S=200 (shfl reductions, 4 barriers)
    int my_id = 0;
    bool valid = false;
    float my_score = -INFINITY;
    if (tid < RD_S) {
        my_id = ids[(size_t)b * RD_S + tid];
        valid = (my_id != RD_PAD_ID) && (my_id != RD_INTEREST_ID);
        my_score = valid ? s_scores[tid] : -INFINITY;
    }

    float m = my_score;
    #pragma unroll
    for (int off = 16; off > 0; off >>= 1)
        m = fmaxf(m, __shfl_xor_sync(0xFFFFFFFFu, m, off));
    if (lane == 0) s_part[warp] = m;
    __syncthreads();
    if (warp == 0) {
        float v = (lane < RD_WARPS) ? s_part[lane] : -INFINITY;
        #pragma unroll
        for (int off = 4; off > 0; off >>= 1)
            v = fmaxf(v, __shfl_xor_sync(0xFFFFFFFFu, v, off));
        if (lane == 0) s_bcast = v;
    }
    __syncthreads();
    const float mx = s_bcast;

    const float e = valid ? __expf(my_score - mx) : 0.0f;
    float sum = e;
    #pragma unroll
    for (int off = 16; off > 0; off >>= 1)
        sum += __shfl_xor_sync(0xFFFFFFFFu, sum, off);
    if (lane == 0) s_part[warp] = sum;
    __syncthreads();
    if (warp == 0) {
        float v = (lane < RD_WARPS) ? s_part[lane] : 0.0f;
        #pragma unroll
        for (int off = 4; off > 0; off >>= 1)
            v += __shfl_xor_sync(0xFFFFFFFFu, v, off);
        if (lane == 0) s_bcast = v;
    }
    __syncthreads();

    // scatter (row zeroed by memset; same-stream order guarantees visibility)
    if (tid < RD_S && valid)
        atomicAdd(out + (size_t)b * RD_VOCAB + my_id, e * (1.0f / s_bcast));
}

extern "C" void kernel_launch(void* const* d_in, const int* in_sizes, int n_in,
                              void* d_out, int out_size)
{
    const float* hidden = (const float*)d_in[0];
    const int*   ids    = (const int*)d_in[1];
    const float* w_proj = (const float*)d_in[2];
    const float* b_proj = (const float*)d_in[3];
    float*       out    = (float*)d_out;

    // Zero the full output via the driver fill path (~7 TB/s observed).
    cudaMemsetAsync(out, 0, (size_t)RD_B * RD_VOCAB * sizeof(float), 0);

    rd_compute_scatter_kernel<<<RD_B, RD_THREADS>>>(hidden, ids, w_proj, b_proj, out);
}

// round 13
// speedup vs baseline: 1.1149x; 1.1149x over previous
#include <cuda_runtime.h>

// RepeatDecoder: B=1024, S=200, H=128, VOCAB=100000
//   features = tanh(hidden + hidden[:,0:1,:])
//   scores   = features @ w_proj + b_proj ; mask PAD/INTEREST -> -inf
//   attn     = softmax(scores, axis=-1)
//   out[b, input_ids[b,s]] += attn[b,s]   (out zero elsewhere)
//
// R12: R9 structure (memset -> fused compute+scatter; best known 86.1us),
//      compute loop made guard-free (12 dual iters + peeled single tail),
//      occupancy pinned via __launch_bounds__(256, 8).
//      Model: memset ~58us (CE/driver fill, ~6.9TB/s) + compute ~21us floor
//      (105MB at the ~5TB/s SM-side DRAM ceiling) => ~81us structural floor.

#define RD_VOCAB 100000
#define RD_PAD_ID (RD_VOCAB - 2)
#define RD_INTEREST_ID (RD_VOCAB - 1)
#define RD_B 1024
#define RD_S 200
#define RD_H 128
#define RD_THREADS 256
#define RD_WARPS (RD_THREADS / 32)

__device__ __forceinline__ float fast_tanhf(float x) {
    float r;
    asm("tanh.approx.f32 %0, %1;" : "=f"(r) : "f"(x));
    return r;
}

__device__ __forceinline__ float dot_tanh4(const float4 h, const float4 k4,
                                           const float4 w4) {
    float p = fast_tanhf(h.x + k4.x) * w4.x;
    p = fmaf(fast_tanhf(h.y + k4.y), w4.y, p);
    p = fmaf(fast_tanhf(h.z + k4.z), w4.z, p);
    p = fmaf(fast_tanhf(h.w + k4.w), w4.w, p);
    return p;
}

// ---------------------------------------------------------------------------
// Compute + scatter: scores -> softmax -> atomics (out pre-zeroed by memset).
// ---------------------------------------------------------------------------
__global__ __launch_bounds__(RD_THREADS, 8)
void rd_compute_scatter_kernel(const float* __restrict__ hidden,
                               const int* __restrict__ ids,
                               const float* __restrict__ w_proj,
                               const float* __restrict__ b_proj,
                               float* __restrict__ out)
{
    __shared__ float s_scores[RD_S];
    __shared__ float s_part[RD_WARPS];
    __shared__ float s_bcast;

    const int b    = blockIdx.x;
    const int tid  = threadIdx.x;
    const int warp = tid >> 5;
    const int lane = tid & 31;

    const float* hb = hidden + (size_t)b * RD_S * RD_H;

    const float4 w4 = reinterpret_cast<const float4*>(w_proj)[lane];
    const float4 k4 = reinterpret_cast<const float4*>(hb)[lane];
    const float  bias = b_proj[0];

    // Guard-free main loop: positions s0 = it*16+warp, s1 = s0+8.
    // Max s1 over it<=11 is 11*16+7+8 = 191 < 200 -> no bounds checks.
    #pragma unroll 1
    for (int it = 0; it < 12; ++it) {
        const int s0 = it * 16 + warp;
        const int s1 = s0 + 8;

        const float4 h0 = reinterpret_cast<const float4*>(hb + s0 * RD_H)[lane];
        const float4 h1 = reinterpret_cast<const float4*>(hb + s1 * RD_H)[lane];

        float p0 = dot_tanh4(h0, k4, w4);
        float p1 = dot_tanh4(h1, k4, w4);

        #pragma unroll
        for (int off = 16; off > 0; off >>= 1) {
            p0 += __shfl_xor_sync(0xFFFFFFFFu, p0, off);
            p1 += __shfl_xor_sync(0xFFFFFFFFu, p1, off);
        }
        if (lane == 0) {
            s_scores[s0] = p0 + bias;
            s_scores[s1] = p1 + bias;
        }
    }
    // Peeled tail: s = 192 + warp (covers 192..199).
    {
        const int s0 = 192 + warp;
        const float4 h0 = reinterpret_cast<const float4*>(hb + s0 * RD_H)[lane];
        float p0 = dot_tanh4(h0, k4, w4);
        #pragma unroll
        for (int off = 16; off > 0; off >>= 1)
            p0 += __shfl_xor_sync(0xFFFFFFFFu, p0, off);
        if (lane == 0) s_scores[s0] = p0 + bias;
    }
    __syncthreads();

    // mask + softmax over S=200 (shfl reductions, 4 barriers)
    int my_id = 0;
    bool valid = false;
    float my_score = -INFINITY;
    if (tid < RD_S) {
        my_id = ids[(size_t)b * RD_S + tid];
        valid = (my_id != RD_PAD_ID) && (my_id != RD_INTEREST_ID);
        my_score = valid ? s_scores[tid] : -INFINITY;
    }

    float m = my_score;
    #pragma unroll
    for (int off = 16; off > 0; off >>= 1)
        m = fmaxf(m, __shfl_xor_sync(0xFFFFFFFFu, m, off));
    if (lane == 0) s_part[warp] = m;
    __syncthreads();
    if (warp == 0) {
        float v = (lane < RD_WARPS) ? s_part[lane] : -INFINITY;
        #pragma unroll
        for (int off = 4; off > 0; off >>= 1)
            v = fmaxf(v, __shfl_xor_sync(0xFFFFFFFFu, v, off));
        if (lane == 0) s_bcast = v;
    }
    __syncthreads();
    const float mx = s_bcast;

    const float e = valid ? __expf(my_score - mx) : 0.0f;
    float sum = e;
    #pragma unroll
    for (int off = 16; off > 0; off >>= 1)
        sum += __shfl_xor_sync(0xFFFFFFFFu, sum, off);
    if (lane == 0) s_part[warp] = sum;
    __syncthreads();
    if (warp == 0) {
        float v = (lane < RD_WARPS) ? s_part[lane] : 0.0f;
        #pragma unroll
        for (int off = 4; off > 0; off >>= 1)
            v += __shfl_xor_sync(0xFFFFFFFFu, v, off);
        if (lane == 0) s_bcast = v;
    }
    __syncthreads();

    // scatter (row zeroed by memset; same-stream order guarantees visibility)
    if (tid < RD_S && valid)
        atomicAdd(out + (size_t)b * RD_VOCAB + my_id, e * (1.0f / s_bcast));
}

extern "C" void kernel_launch(void* const* d_in, const int* in_sizes, int n_in,
                              void* d_out, int out_size)
{
    const float* hidden = (const float*)d_in[0];
    const int*   ids    = (const int*)d_in[1];
    const float* w_proj = (const float*)d_in[2];
    const float* b_proj = (const float*)d_in[3];
    float*       out    = (float*)d_out;

    // Zero the full output via the driver fill path (~6.9 TB/s observed).
    cudaMemsetAsync(out, 0, (size_t)RD_B * RD_VOCAB * sizeof(float), 0);

    rd_compute_scatter_kernel<<<RD_B, RD_THREADS>>>(hidden, ids, w_proj, b_proj, out);
}

// round 14
// speedup vs baseline: 1.1429x; 1.0252x over previous
#include <cuda_runtime.h>

// RepeatDecoder: B=1024, S=200, H=128, VOCAB=100000
//   features = tanh(hidden + hidden[:,0:1,:])
//   scores   = features @ w_proj + b_proj ; mask PAD/INTEREST -> -inf
//   attn     = softmax(scores, axis=-1)
//   out[b, input_ids[b,s]] += attn[b,s]   (out zero elsewhere)
//
// R14: memset -> score kernel (one warp per position-pair, 102400 warps, no
//      loop: load latency amortized by block-level parallelism instead of
//      per-thread ILP) -> softmax+scatter kernel (scores are L2 hits).

#define RD_VOCAB 100000
#define RD_PAD_ID (RD_VOCAB - 2)
#define RD_INTEREST_ID (RD_VOCAB - 1)
#define RD_B 1024
#define RD_S 200
#define RD_H 128
#define RD_THREADS 256
#define RD_WARPS (RD_THREADS / 32)
#define RD_PAIRS (RD_B * RD_S / 2)          // 102400 warp-tasks
#define RD_SCORE_BLOCKS (RD_PAIRS / RD_WARPS)  // 12800

// Per-position scores (+bias). 800 KB static; L2-resident between kernels.
__device__ float g_scores[RD_B * RD_S];

__device__ __forceinline__ float fast_tanhf(float x) {
    float r;
    asm("tanh.approx.f32 %0, %1;" : "=f"(r) : "f"(x));
    return r;
}

__device__ __forceinline__ float dot_tanh4(const float4 h, const float4 k4,
                                           const float4 w4) {
    float p = fast_tanhf(h.x + k4.x) * w4.x;
    p = fmaf(fast_tanhf(h.y + k4.y), w4.y, p);
    p = fmaf(fast_tanhf(h.z + k4.z), w4.z, p);
    p = fmaf(fast_tanhf(h.w + k4.w), w4.w, p);
    return p;
}

// ---------------------------------------------------------------------------
// Kernel A: scores. One warp per pair (b, s), (b, s+1). No loops -> every
// warp issues its 3 independent 512B loads immediately; chip-wide MLP huge.
// ---------------------------------------------------------------------------
__global__ __launch_bounds__(RD_THREADS)
void rd_score_kernel(const float* __restrict__ hidden,
                     const float* __restrict__ w_proj,
                     const float* __restrict__ b_proj)
{
    const int q    = blockIdx.x * RD_WARPS + (threadIdx.x >> 5);
    const int lane = threadIdx.x & 31;

    const int b = q / (RD_S / 2);           // 100 pairs per batch
    const int s = (q % (RD_S / 2)) * 2;

    const float* hb = hidden + (size_t)b * RD_S * RD_H;

    // independent loads: key row (L1/L2 hit after first warp), two h rows
    const float4 k4 = reinterpret_cast<const float4*>(hb)[lane];
    const float4 h0 = __ldcs(&reinterpret_cast<const float4*>(hb + s * RD_H)[lane]);
    const float4 h1 = __ldcs(&reinterpret_cast<const float4*>(hb + (s + 1) * RD_H)[lane]);
    const float4 w4 = reinterpret_cast<const float4*>(w_proj)[lane];
    const float  bias = b_proj[0];

    float p0 = dot_tanh4(h0, k4, w4);
    float p1 = dot_tanh4(h1, k4, w4);

    #pragma unroll
    for (int off = 16; off > 0; off >>= 1) {
        p0 += __shfl_xor_sync(0xFFFFFFFFu, p0, off);
        p1 += __shfl_xor_sync(0xFFFFFFFFu, p1, off);
    }
    if (lane == 0) {
        // q*2 == b*RD_S + s
        float2* dst = reinterpret_cast<float2*>(&g_scores[2 * q]);
        *dst = make_float2(p0 + bias, p1 + bias);
    }
}

// ---------------------------------------------------------------------------
// Kernel B: per-batch softmax over L2-hit scores + scatter atomics.
// ---------------------------------------------------------------------------
__global__ __launch_bounds__(RD_THREADS)
void rd_softmax_scatter_kernel(const int* __restrict__ ids,
                               float* __restrict__ out)
{
    __shared__ float s_part[RD_WARPS];
    __shared__ float s_bcast;

    const int b    = blockIdx.x;
    const int tid  = threadIdx.x;
    const int warp = tid >> 5;
    const int lane = tid & 31;

    int my_id = 0;
    bool valid = false;
    float my_score = -INFINITY;
    if (tid < RD_S) {
        my_id = ids[(size_t)b * RD_S + tid];
        valid = (my_id != RD_PAD_ID) && (my_id != RD_INTEREST_ID);
        if (valid) my_score = g_scores[(size_t)b * RD_S + tid];
    }

    float m = my_score;
    #pragma unroll
    for (int off = 16; off > 0; off >>= 1)
        m = fmaxf(m, __shfl_xor_sync(0xFFFFFFFFu, m, off));
    if (lane == 0) s_part[warp] = m;
    __syncthreads();
    if (warp == 0) {
        float v = (lane < RD_WARPS) ? s_part[lane] : -INFINITY;
        #pragma unroll
        for (int off = 4; off > 0; off >>= 1)
            v = fmaxf(v, __shfl_xor_sync(0xFFFFFFFFu, v, off));
        if (lane == 0) s_bcast = v;
    }
    __syncthreads();
    const float mx = s_bcast;

    const float e = valid ? __expf(my_score - mx) : 0.0f;
    float sum = e;
    #pragma unroll
    for (int off = 16; off > 0; off >>= 1)
        sum += __shfl_xor_sync(0xFFFFFFFFu, sum, off);
    if (lane == 0) s_part[warp] = sum;
    __syncthreads();
    if (warp == 0) {
        float v = (lane < RD_WARPS) ? s_part[lane] : 0.0f;
        #pragma unroll
        for (int off = 4; off > 0; off >>= 1)
            v += __shfl_xor_sync(0xFFFFFFFFu, v, off);
        if (lane == 0) s_bcast = v;
    }
    __syncthreads();

    if (tid < RD_S && valid)
        atomicAdd(out + (size_t)b * RD_VOCAB + my_id, e * (1.0f / s_bcast));
}

extern "C" void kernel_launch(void* const* d_in, const int* in_sizes, int n_in,
                              void* d_out, int out_size)
{
    const float* hidden = (const float*)d_in[0];
    const int*   ids    = (const int*)d_in[1];
    const float* w_proj = (const float*)d_in[2];
    const float* b_proj = (const float*)d_in[3];
    float*       out    = (float*)d_out;

    // Zero the full output via the driver fill path (~6.8 TB/s observed).
    cudaMemsetAsync(out, 0, (size_t)RD_B * RD_VOCAB * sizeof(float), 0);

    rd_score_kernel<<<RD_SCORE_BLOCKS, RD_THREADS>>>(hidden, w_proj, b_proj);
    rd_softmax_scatter_kernel<<<RD_B, RD_THREADS>>>(ids, out);
}